// round 11
// baseline (speedup 1.0000x reference)
#include <cuda_runtime.h>
#include <math.h>
#include <stdint.h>

// Problem constants: B=8192 rows, H=4096 hidden, E=8 experts, TOP_K=2. fp32.
#define B_ROWS 8192
#define HDIM   4096

// Partial gate scores: g_part[row*16 + half*8 + e]  (half = which H-2048 slice)
__device__ float g_part[(size_t)B_ROWS * 16];

// Packed f32x2 helpers (sm_10x packed fp32 pipe, PTX-only)
#define FMA2(d, a, b, c) asm("fma.rn.f32x2 %0, %1, %2, %3;" : "=l"(d) : "l"(a), "l"(b), "l"(c))
#define ADD2(d, a, b)    asm("add.rn.f32x2 %0, %1, %2;"     : "=l"(d) : "l"(a), "l"(b))
#define PACK2(d, x)      asm("mov.b64 %0, {%1, %1};"        : "=l"(d) : "r"(x))
#define UNPK2(lo, hi, s) asm("mov.b64 {%0, %1}, %2;"        : "=r"(lo), "=r"(hi) : "l"(s))

// mbarrier / bulk-copy PTX
#define MBAR_INIT(a, n) \
    asm volatile("mbarrier.init.shared.b64 [%0], %1;" :: "r"(a), "r"(n) : "memory")
#define MBAR_EXPECT_TX(a, n) \
    asm volatile("mbarrier.arrive.expect_tx.shared.b64 _, [%0], %1;" :: "r"(a), "r"(n) : "memory")
#define MBAR_ARRIVE(a) \
    asm volatile("mbarrier.arrive.shared.b64 _, [%0];" :: "r"(a) : "memory")
#define MBAR_WAIT(a, par) do {                                                   \
    asm volatile(                                                                \
        "{\n\t.reg .pred P1;\n\t"                                                \
        "WL_%=:\n\t"                                                             \
        "mbarrier.try_wait.parity.acquire.cta.shared::cta.b64 P1, [%0], %1, 0x989680;\n\t" \
        "@P1 bra.uni WD_%=;\n\t"                                                 \
        "bra.uni WL_%=;\n\t"                                                     \
        "WD_%=:\n\t}"                                                            \
        :: "r"(a), "r"(par) : "memory");                                         \
} while (0)
#define BULK_G2S(dst, src, bytes, mbar) \
    asm volatile("cp.async.bulk.shared::cta.global.mbarrier::complete_tx::bytes " \
                 "[%0], [%1], %2, [%3];" \
                 :: "r"(dst), "l"(src), "r"(bytes), "r"(mbar) : "memory")

static __device__ __forceinline__ uint32_t smem_u32(const void* p) {
    uint32_t a;
    asm("{ .reg .u64 t; cvta.to.shared.u64 t, %1; cvt.u32.u64 %0, t; }" : "=r"(a) : "l"(p));
    return a;
}

// ---------------------------------------------------------------------------
// Kernel 1: gate partials. grid = 256 blocks x 544 threads.
// Block (g*2 + half) owns rows [g*64, g*64+64) and the H-half [half*2048, +2048).
// Warp 16 = producer: cp.async.bulk streams 8KB half-rows into a 4-stage smem
// ring (runs 4 rows ahead -> 32KB/block in DRAM flight, no prefetch regs).
// Warps 0-15 = consumers: thread t owns h = half*2048 + 4t..+3; its 32 gate
// weights live in 16 packed f32x2 registers, loaded ONCE (this kernel stays
// under ~60 live regs -> no spills, unlike the previous 64-reg-capped version).
// Per row: LDS float4 from ring, 16 packed FMAs, 9-shfl distribute-reduce
// (lane l ends holding expert bitrev3(l) warp-summed). Phases of 4 rows share
// one named-barrier pair (bar.sync 1,512 — producer never joins); stage 2
// reduces all 4x8 (row,expert) partials across the 16 warps in parallel and
// writes g_part. Top-2 + softmax happen in the combine kernel.
// ---------------------------------------------------------------------------
__global__ __launch_bounds__(544) void gate_kernel(
    const float* __restrict__ hidden,
    const float* __restrict__ gw)     // (H, E) row-major
{
    __shared__ __align__(16) float s_tile[4][2048];   // 4-stage ring, 8KB/stage
    __shared__ float s_part[4][16][9];                // [row][warp][expert], pad 9
    __shared__ __align__(8) unsigned long long s_mbar[8];  // full[0..3], empty[4..7]

    const int t    = threadIdx.x;
    const int half = (int)blockIdx.x & 1;
    const int base_row = ((int)blockIdx.x >> 1) * 64;

    const uint32_t mb = smem_u32(s_mbar);

    if (t == 0) {
#pragma unroll
        for (int s = 0; s < 4; s++) {
            MBAR_INIT(mb + s * 8, 1);           // full[s]: tx-completed
            MBAR_INIT(mb + 32 + s * 8, 1);      // empty[s]: 1 release arrive
        }
        asm volatile("fence.proxy.async.shared::cta;" ::: "memory");
    }
    __syncthreads();

    if (t >= 512) {
        // ---- producer warp: only lane 0 works ----
        if (t == 512) {
            const char* src = reinterpret_cast<const char*>(
                hidden + (size_t)base_row * HDIM + (size_t)half * 2048);
            const uint32_t tile0 = smem_u32(s_tile);
            for (int r = 0; r < 64; r++) {
                const int s = r & 3;
                const int ph = ((r >> 2) & 1) ^ 1;   // first wait passes on fresh mbar
                MBAR_WAIT(mb + 32 + s * 8, ph);
                MBAR_EXPECT_TX(mb + s * 8, 8192);
                BULK_G2S(tile0 + s * 8192, src + (size_t)r * (HDIM * 4), 8192,
                         mb + s * 8);
            }
        }
        return;
    }

    // ---- consumers: warps 0-15 ----
    const int lane = t & 31;
    const int wid  = t >> 5;
    // expert index held by this lane after the distribute-reduce: bitrev3(lane)
    const int e_lane = ((lane & 1) << 2) | (lane & 2) | ((lane >> 2) & 1);

    // 32 contiguous gate weights for this thread's 4 h positions -> 16 f32x2.
    long long g2[16];
    {
        const long long* gwp =
            reinterpret_cast<const long long*>(gw) + ((size_t)half * 512 + t) * 16;
#pragma unroll
        for (int i = 0; i < 16; i++) g2[i] = gwp[i];
    }

    for (int phi = 0; phi < 16; phi++) {         // 16 phases x 4 rows = 64 rows
        const int par = phi & 1;
#pragma unroll
        for (int j = 0; j < 4; j++) {
            MBAR_WAIT(mb + j * 8, par);
            const float4 v = *reinterpret_cast<const float4*>(&s_tile[j][t * 4]);

            long long acc0 = 0, acc1 = 0, acc2 = 0, acc3 = 0;
            const float vk[4] = {v.x, v.y, v.z, v.w};
#pragma unroll
            for (int k = 0; k < 4; k++) {
                long long pv;
                PACK2(pv, __float_as_int(vk[k]));
                FMA2(acc0, pv, g2[k * 4 + 0], acc0);
                FMA2(acc1, pv, g2[k * 4 + 1], acc1);
                FMA2(acc2, pv, g2[k * 4 + 2], acc2);
                FMA2(acc3, pv, g2[k * 4 + 3], acc3);
            }
            {   // level 0: xor 1
                const bool hi = lane & 1;
                long long s0 = hi ? acc0 : acc2;
                long long s1 = hi ? acc1 : acc3;
                long long q0 = __shfl_xor_sync(0xffffffffu, s0, 1);
                long long q1 = __shfl_xor_sync(0xffffffffu, s1, 1);
                long long k0 = hi ? acc2 : acc0;
                long long k1 = hi ? acc3 : acc1;
                ADD2(acc0, k0, q0);
                ADD2(acc1, k1, q1);
            }
            {   // level 1: xor 2
                const bool hi = lane & 2;
                long long s0 = hi ? acc0 : acc1;
                long long q0 = __shfl_xor_sync(0xffffffffu, s0, 2);
                long long k0 = hi ? acc1 : acc0;
                ADD2(acc0, k0, q0);
            }
            float val;
            {   // level 2: xor 4, unpack
                int lo_i, hi_i;
                UNPK2(lo_i, hi_i, acc0);
                const float f0 = __int_as_float(lo_i);
                const float f1 = __int_as_float(hi_i);
                const bool hi = lane & 4;
                const float s = hi ? f0 : f1;
                const float q = __shfl_xor_sync(0xffffffffu, s, 4);
                val = (hi ? f1 : f0) + q;
            }
            val += __shfl_xor_sync(0xffffffffu, val, 8);
            val += __shfl_xor_sync(0xffffffffu, val, 16);

            if (lane < 8) s_part[j][wid][e_lane] = val;
        }
        asm volatile("bar.sync 1, 512;" ::: "memory");

        // stage 2: 32 (row,expert) reductions of 16 warp-partials each;
        // warp w handles pair ids w and w+16.
#pragma unroll
        for (int it = 0; it < 2; it++) {
            const int pid = wid + it * 16;
            const int row = pid >> 3;
            const int e   = pid & 7;
            float p = (lane < 16) ? s_part[row][lane][e] : 0.0f;
            p += __shfl_xor_sync(0xffffffffu, p, 8);
            p += __shfl_xor_sync(0xffffffffu, p, 4);
            p += __shfl_xor_sync(0xffffffffu, p, 2);
            p += __shfl_xor_sync(0xffffffffu, p, 1);
            if (lane == 0)
                g_part[(size_t)(base_row + phi * 4 + row) * 16 + half * 8 + e] = p;
        }
        asm volatile("bar.sync 1, 512;" ::: "memory");

        // release the 4 ring stages for the producer
        if (t < 4) MBAR_ARRIVE(mb + 32 + t * 8);
    }
}

// ---------------------------------------------------------------------------
// Kernel 2: finalize top-2 + combine. One block per row, 256 threads.
// Warp 0 preamble: score[e] = part[half0] + part[half1] + bias, shfl top-2
// with smallest-index tie-break (matches lax.top_k), 2-way softmax
// (== softmax over 8 + top-2 renorm). Then streaming combine:
// out[b,:] = p0*eo[i0,b,:] + p1*eo[i1,b,:], float4, 8 loads in flight,
// .cs hints (no reuse).
// ---------------------------------------------------------------------------
__global__ __launch_bounds__(256) void combine_kernel(
    const float* __restrict__ eo,
    const float* __restrict__ gb,
    float* __restrict__ out)
{
    const int b = (int)blockIdx.x;
    __shared__ float4 bc;

    if (threadIdx.x < 32) {
        const int lane = threadIdx.x;
        float s = -3.402823466e38f;
        if (lane < 8)
            s = g_part[(size_t)b * 16 + lane] + g_part[(size_t)b * 16 + 8 + lane]
                + gb[lane];

        float v1 = s; int i1 = lane;
#pragma unroll
        for (int off = 4; off; off >>= 1) {
            const float ov = __shfl_xor_sync(0xffffffffu, v1, off);
            const int   oi = __shfl_xor_sync(0xffffffffu, i1, off);
            if (ov > v1 || (ov == v1 && oi < i1)) { v1 = ov; i1 = oi; }
        }
        float v2 = (lane == i1) ? -3.402823466e38f : s;
        int i2 = lane;
#pragma unroll
        for (int off = 4; off; off >>= 1) {
            const float ov = __shfl_xor_sync(0xffffffffu, v2, off);
            const int   oi = __shfl_xor_sync(0xffffffffu, i2, off);
            if (ov > v2 || (ov == v2 && oi < i2)) { v2 = ov; i2 = oi; }
        }
        if (lane == 0) {
            const float p1 = 1.0f / (1.0f + expf(v2 - v1));
            bc = make_float4(p1, 1.0f - p1, __int_as_float(i1), __int_as_float(i2));
        }
    }
    __syncthreads();

    const float4 rg = bc;
    const float p0 = rg.x, p1 = rg.y;
    const int i0 = __float_as_int(rg.z);
    const int i1 = __float_as_int(rg.w);

    const float4* e0 =
        reinterpret_cast<const float4*>(eo + ((size_t)i0 * B_ROWS + b) * HDIM);
    const float4* e1 =
        reinterpret_cast<const float4*>(eo + ((size_t)i1 * B_ROWS + b) * HDIM);
    float4* o = reinterpret_cast<float4*>(out + (size_t)b * HDIM);

    const int t = threadIdx.x;
    float4 a[4], c[4];
#pragma unroll
    for (int k = 0; k < 4; k++) {
        a[k] = __ldcs(&e0[t + k * 256]);
        c[k] = __ldcs(&e1[t + k * 256]);
    }
#pragma unroll
    for (int k = 0; k < 4; k++) {
        float4 r;
        r.x = p0 * a[k].x + p1 * c[k].x;
        r.y = p0 * a[k].y + p1 * c[k].y;
        r.z = p0 * a[k].z + p1 * c[k].z;
        r.w = p0 * a[k].w + p1 * c[k].w;
        __stcs(&o[t + k * 256], r);
    }
}

// ---------------------------------------------------------------------------
// Launch. Inputs (metadata order): hidden_states (B,H) f32, expert_outputs
// (E,B,H) f32, gate_w (H,E) f32, gate_b (E,) f32. Output: (B,H) f32.
// Graph-capturable: two kernel launches, no allocs, no syncs.
// ---------------------------------------------------------------------------
extern "C" void kernel_launch(void* const* d_in, const int* in_sizes, int n_in,
                              void* d_out, int out_size)
{
    const float* hidden = (const float*)d_in[0];
    const float* eo     = (const float*)d_in[1];
    const float* gw     = (const float*)d_in[2];
    const float* gb     = (const float*)d_in[3];
    float* out = (float*)d_out;

    gate_kernel<<<256, 544>>>(hidden, gw);
    combine_kernel<<<B_ROWS, 256>>>(eo, gb, out);
}

// round 13
// speedup vs baseline: 1.0116x; 1.0116x over previous
#include <cuda_runtime.h>
#include <math.h>
#include <stdint.h>

// Problem constants: B=8192 rows, H=4096 hidden, E=8 experts, TOP_K=2. fp32.
#define B_ROWS 8192
#define HDIM   4096
#define RPB    128     // rows per gate block

// Partial gate scores: g_part[row*16 + half*8 + e]  (half = which H-2048 slice)
__device__ float g_part[(size_t)B_ROWS * 16];

// Packed f32x2 helpers (sm_10x packed fp32 pipe, PTX-only)
#define FMA2(d, a, b, c) asm("fma.rn.f32x2 %0, %1, %2, %3;" : "=l"(d) : "l"(a), "l"(b), "l"(c))
#define ADD2(d, a, b)    asm("add.rn.f32x2 %0, %1, %2;"     : "=l"(d) : "l"(a), "l"(b))
#define PACK2(d, x)      asm("mov.b64 %0, {%1, %1};"        : "=l"(d) : "r"(x))
#define UNPK2(lo, hi, s) asm("mov.b64 {%0, %1}, %2;"        : "=r"(lo), "=r"(hi) : "l"(s))

// mbarrier / bulk-copy PTX
#define MBAR_INIT(a, n) \
    asm volatile("mbarrier.init.shared.b64 [%0], %1;" :: "r"(a), "r"(n) : "memory")
#define MBAR_EXPECT_TX(a, n) \
    asm volatile("mbarrier.arrive.expect_tx.shared.b64 _, [%0], %1;" :: "r"(a), "r"(n) : "memory")
#define MBAR_ARRIVE(a) \
    asm volatile("mbarrier.arrive.shared.b64 _, [%0];" :: "r"(a) : "memory")
#define MBAR_WAIT(a, par) do {                                                   \
    asm volatile(                                                                \
        "{\n\t.reg .pred P1;\n\t"                                                \
        "WL_%=:\n\t"                                                             \
        "mbarrier.try_wait.parity.acquire.cta.shared::cta.b64 P1, [%0], %1, 0x989680;\n\t" \
        "@P1 bra.uni WD_%=;\n\t"                                                 \
        "bra.uni WL_%=;\n\t"                                                     \
        "WD_%=:\n\t}"                                                            \
        :: "r"(a), "r"(par) : "memory");                                         \
} while (0)
#define BULK_G2S(dst, src, bytes, mbar) \
    asm volatile("cp.async.bulk.shared::cta.global.mbarrier::complete_tx::bytes " \
                 "[%0], [%1], %2, [%3];" \
                 :: "r"(dst), "l"(src), "r"(bytes), "r"(mbar) : "memory")

static __device__ __forceinline__ uint32_t smem_u32(const void* p) {
    uint32_t a;
    asm("{ .reg .u64 t; cvta.to.shared.u64 t, %1; cvt.u32.u64 %0, t; }" : "=r"(a) : "l"(p));
    return a;
}

// No-op kernel: shifts ncu's skip-5 capture onto gate_kernel.
// Pattern per call: dummy, gate, dummy, combine -> idx 5 mod 4 == 1 == gate.
__global__ void dummy_kernel() {}

// ---------------------------------------------------------------------------
// Kernel 1: gate partials. grid = 128 blocks x 544 threads (single wave).
// Block (g*2 + half) owns rows [g*128, g*128+128) and H-half [half*2048,+2048).
// Warp 16 = producer: cp.async.bulk streams 8KB half-rows into an 8-stage
// smem ring (32KB of DRAM traffic in flight while the other 4 stages are
// being consumed).
// Warps 0-15 = consumers: thread t owns h = half*2048 + 4t..+3; its 32 gate
// weights live in 16 packed f32x2 registers, loaded once. Per row: LDS float4
// from the ring, 16 packed FMAs, 9-shfl distribute-reduce (lane l holds
// expert bitrev3(l) warp-summed). One named barrier (bar.sync 1,512) per
// group of 4 rows; IMMEDIATELY after it, threads 0-3 release the group's 4
// ring stages (barrier proves every warp's LDS of those stages completed ->
// race-free by construction, unlike the R12 per-warp early release). The
// producer refills those stages while consumers run stage-2 reduction and
// the next 4 rows. s_part is double-buffered so stage 2 needs no trailing
// barrier. Top-2 + softmax happen in the combine kernel.
// ---------------------------------------------------------------------------
__global__ __launch_bounds__(544, 1) void gate_kernel(
    const float* __restrict__ hidden,
    const float* __restrict__ gw)     // (H, E) row-major
{
    __shared__ __align__(16) float s_tile[8][2048];   // 8-stage ring, 64KB
    __shared__ float s_part[2][4][16][9];             // [buf][row][warp][e], pad 9
    __shared__ __align__(8) unsigned long long s_mbar[16];  // full[0..7], empty[8..15]

    const int t    = threadIdx.x;
    const int half = (int)blockIdx.x & 1;
    const int base_row = ((int)blockIdx.x >> 1) * RPB;

    const uint32_t mb = smem_u32(s_mbar);
    const uint32_t tile0 = smem_u32(s_tile);

    if (t == 0) {
#pragma unroll
        for (int s = 0; s < 8; s++) {
            MBAR_INIT(mb + s * 8, 1);            // full[s]: completed by bulk tx
            MBAR_INIT(mb + 64 + s * 8, 1);       // empty[s]: 1 release arrival
        }
        asm volatile("fence.proxy.async.shared::cta;" ::: "memory");
    }
    __syncthreads();

    if (t >= 512) {
        // ---- producer warp: lane 0 only, runs up to 8 rows ahead ----
        if (t == 512) {
            const char* src = reinterpret_cast<const char*>(
                hidden + (size_t)base_row * HDIM + (size_t)half * 2048);
            for (int r = 0; r < RPB; r++) {
                const int s = r & 7;
                const int ph = ((r >> 3) & 1) ^ 1;  // fresh-mbar: first 8 pass
                MBAR_WAIT(mb + 64 + s * 8, ph);
                MBAR_EXPECT_TX(mb + s * 8, 8192);
                BULK_G2S(tile0 + s * 8192, src + (size_t)r * (HDIM * 4), 8192,
                         mb + s * 8);
            }
        }
        return;
    }

    // ---- consumers: warps 0-15 ----
    const int lane = t & 31;
    const int wid  = t >> 5;
    // expert index held by this lane after the distribute-reduce: bitrev3(lane)
    const int e_lane = ((lane & 1) << 2) | (lane & 2) | ((lane >> 2) & 1);

    // 32 contiguous gate weights for this thread's 4 h positions -> 16 f32x2.
    long long g2[16];
    {
        const long long* gwp =
            reinterpret_cast<const long long*>(gw) + ((size_t)half * 512 + t) * 16;
#pragma unroll
        for (int i = 0; i < 16; i++) g2[i] = gwp[i];
    }

    for (int r = 0; r < RPB; r++) {
        const int s   = r & 7;
        const int par = (r >> 3) & 1;
        MBAR_WAIT(mb + s * 8, par);
        const float4 v = *reinterpret_cast<const float4*>(&s_tile[s][t * 4]);

        // acc_j holds experts {2j, 2j+1} packed. 0LL == {0.0f, 0.0f}.
        long long acc0 = 0, acc1 = 0, acc2 = 0, acc3 = 0;
        const float vk[4] = {v.x, v.y, v.z, v.w};
#pragma unroll
        for (int k = 0; k < 4; k++) {
            long long pv;
            PACK2(pv, __float_as_int(vk[k]));
            FMA2(acc0, pv, g2[k * 4 + 0], acc0);
            FMA2(acc1, pv, g2[k * 4 + 1], acc1);
            FMA2(acc2, pv, g2[k * 4 + 2], acc2);
            FMA2(acc3, pv, g2[k * 4 + 3], acc3);
        }
        {   // level 0: xor 1
            const bool hi = lane & 1;
            long long s0 = hi ? acc0 : acc2;
            long long s1 = hi ? acc1 : acc3;
            long long q0 = __shfl_xor_sync(0xffffffffu, s0, 1);
            long long q1 = __shfl_xor_sync(0xffffffffu, s1, 1);
            long long k0 = hi ? acc2 : acc0;
            long long k1 = hi ? acc3 : acc1;
            ADD2(acc0, k0, q0);
            ADD2(acc1, k1, q1);
        }
        {   // level 1: xor 2
            const bool hi = lane & 2;
            long long s0 = hi ? acc0 : acc1;
            long long q0 = __shfl_xor_sync(0xffffffffu, s0, 2);
            long long k0 = hi ? acc1 : acc0;
            ADD2(acc0, k0, q0);
        }
        float val;
        {   // level 2: xor 4, unpack
            int lo_i, hi_i;
            UNPK2(lo_i, hi_i, acc0);
            const float f0 = __int_as_float(lo_i);
            const float f1 = __int_as_float(hi_i);
            const bool hi = lane & 4;
            const float sv = hi ? f0 : f1;
            const float q = __shfl_xor_sync(0xffffffffu, sv, 4);
            val = (hi ? f1 : f0) + q;
        }
        val += __shfl_xor_sync(0xffffffffu, val, 8);
        val += __shfl_xor_sync(0xffffffffu, val, 16);

        const int buf = (r >> 2) & 1;
        if (lane < 8) s_part[buf][r & 3][wid][e_lane] = val;

        if ((r & 3) == 3) {
            asm volatile("bar.sync 1, 512;" ::: "memory");
            // Barrier proves all 16 warps finished their LDS of the group's
            // stages -> release them NOW so the producer overlaps our stage-2
            // work and the next 4 rows. Group stages are gs..gs+3, gs = r&4.
            const int gs = r & 4;
            if (t < 4) MBAR_ARRIVE(mb + 64 + (gs + t) * 8);

            // stage 2: 32 (row,expert) reductions of 16 warp-partials each.
            // Double-buffered s_part -> no trailing barrier needed.
#pragma unroll
            for (int it = 0; it < 2; it++) {
                const int pid  = wid + it * 16;
                const int row4 = pid >> 3;
                const int e    = pid & 7;
                float p = (lane < 16) ? s_part[buf][row4][lane][e] : 0.0f;
                p += __shfl_xor_sync(0xffffffffu, p, 8);
                p += __shfl_xor_sync(0xffffffffu, p, 4);
                p += __shfl_xor_sync(0xffffffffu, p, 2);
                p += __shfl_xor_sync(0xffffffffu, p, 1);
                if (lane == 0)
                    g_part[(size_t)(base_row + (r - 3) + row4) * 16 + half * 8 + e] = p;
            }
        }
    }
}

// ---------------------------------------------------------------------------
// Kernel 2: finalize top-2 + combine. One block per row, 256 threads.
// Warp 0 preamble: score[e] = part[half0] + part[half1] + bias, shfl top-2
// with smallest-index tie-break (matches lax.top_k), 2-way softmax
// (== softmax over 8 + top-2 renorm). Then streaming combine:
// out[b,:] = p0*eo[i0,b,:] + p1*eo[i1,b,:], float4, 8 loads in flight,
// .cs hints (no reuse).
// ---------------------------------------------------------------------------
__global__ __launch_bounds__(256) void combine_kernel(
    const float* __restrict__ eo,
    const float* __restrict__ gb,
    float* __restrict__ out)
{
    const int b = (int)blockIdx.x;
    __shared__ float4 bc;

    if (threadIdx.x < 32) {
        const int lane = threadIdx.x;
        float s = -3.402823466e38f;
        if (lane < 8)
            s = g_part[(size_t)b * 16 + lane] + g_part[(size_t)b * 16 + 8 + lane]
                + gb[lane];

        float v1 = s; int i1 = lane;
#pragma unroll
        for (int off = 4; off; off >>= 1) {
            const float ov = __shfl_xor_sync(0xffffffffu, v1, off);
            const int   oi = __shfl_xor_sync(0xffffffffu, i1, off);
            if (ov > v1 || (ov == v1 && oi < i1)) { v1 = ov; i1 = oi; }
        }
        float v2 = (lane == i1) ? -3.402823466e38f : s;
        int i2 = lane;
#pragma unroll
        for (int off = 4; off; off >>= 1) {
            const float ov = __shfl_xor_sync(0xffffffffu, v2, off);
            const int   oi = __shfl_xor_sync(0xffffffffu, i2, off);
            if (ov > v2 || (ov == v2 && oi < i2)) { v2 = ov; i2 = oi; }
        }
        if (lane == 0) {
            const float p1 = 1.0f / (1.0f + expf(v2 - v1));
            bc = make_float4(p1, 1.0f - p1, __int_as_float(i1), __int_as_float(i2));
        }
    }
    __syncthreads();

    const float4 rg = bc;
    const float p0 = rg.x, p1 = rg.y;
    const int i0 = __float_as_int(rg.z);
    const int i1 = __float_as_int(rg.w);

    const float4* e0 =
        reinterpret_cast<const float4*>(eo + ((size_t)i0 * B_ROWS + b) * HDIM);
    const float4* e1 =
        reinterpret_cast<const float4*>(eo + ((size_t)i1 * B_ROWS + b) * HDIM);
    float4* o = reinterpret_cast<float4*>(out + (size_t)b * HDIM);

    const int t = threadIdx.x;
    float4 a[4], c[4];
#pragma unroll
    for (int k = 0; k < 4; k++) {
        a[k] = __ldcs(&e0[t + k * 256]);
        c[k] = __ldcs(&e1[t + k * 256]);
    }
#pragma unroll
    for (int k = 0; k < 4; k++) {
        float4 r;
        r.x = p0 * a[k].x + p1 * c[k].x;
        r.y = p0 * a[k].y + p1 * c[k].y;
        r.z = p0 * a[k].z + p1 * c[k].z;
        r.w = p0 * a[k].w + p1 * c[k].w;
        __stcs(&o[t + k * 256], r);
    }
}

// ---------------------------------------------------------------------------
// Launch. Inputs (metadata order): hidden_states (B,H) f32, expert_outputs
// (E,B,H) f32, gate_w (H,E) f32, gate_b (E,) f32. Output: (B,H) f32.
// Pattern (dummy, gate, dummy, combine): ncu's skip-5 capture lands on
// gate_kernel (index 5 mod 4 == 1). Graph-capturable, no allocs, no syncs.
// ---------------------------------------------------------------------------
extern "C" void kernel_launch(void* const* d_in, const int* in_sizes, int n_in,
                              void* d_out, int out_size)
{
    const float* hidden = (const float*)d_in[0];
    const float* eo     = (const float*)d_in[1];
    const float* gw     = (const float*)d_in[2];
    const float* gb     = (const float*)d_in[3];
    float* out = (float*)d_out;

    dummy_kernel<<<1, 32>>>();
    gate_kernel<<<128, 544>>>(hidden, gw);
    dummy_kernel<<<1, 32>>>();
    combine_kernel<<<B_ROWS, 256>>>(eo, gb, out);
}

// round 14
// speedup vs baseline: 1.2038x; 1.1900x over previous
#include <cuda_runtime.h>
#include <math.h>
#include <stdint.h>

// Problem constants: B=8192 rows, H=4096 hidden, E=8 experts, TOP_K=2. fp32.
#define B_ROWS 8192
#define HDIM   4096
#define RPB    128     // rows per gate block
#define NGRP   (RPB / 4)

// Dynamic smem layout: 16 row-stages (8KB each) + s_part + mbarriers
#define SM_TILE_BYTES  (16 * 8192)                     // 131072
#define SM_PART_OFF    SM_TILE_BYTES
#define SM_PART_BYTES  (2 * 4 * 16 * 9 * 4)            // 4608
#define SM_MBAR_OFF    (SM_PART_OFF + SM_PART_BYTES)   // 135680 (8-aligned)
#define SMEM_BYTES     (SM_MBAR_OFF + 8 * 8)

// Partial gate scores: g_part[row*16 + half*8 + e]  (half = which H-2048 slice)
__device__ float g_part[(size_t)B_ROWS * 16];

// Packed f32x2 helpers (sm_10x packed fp32 pipe, PTX-only)
#define FMA2(d, a, b, c) asm("fma.rn.f32x2 %0, %1, %2, %3;" : "=l"(d) : "l"(a), "l"(b), "l"(c))
#define ADD2(d, a, b)    asm("add.rn.f32x2 %0, %1, %2;"     : "=l"(d) : "l"(a), "l"(b))
#define PACK2(d, x)      asm("mov.b64 %0, {%1, %1};"        : "=l"(d) : "r"(x))
#define UNPK2(lo, hi, s) asm("mov.b64 {%0, %1}, %2;"        : "=r"(lo), "=r"(hi) : "l"(s))

// mbarrier / bulk-copy PTX
#define MBAR_INIT(a, n) \
    asm volatile("mbarrier.init.shared.b64 [%0], %1;" :: "r"(a), "r"(n) : "memory")
#define MBAR_EXPECT_TX(a, n) \
    asm volatile("mbarrier.arrive.expect_tx.shared.b64 _, [%0], %1;" :: "r"(a), "r"(n) : "memory")
#define MBAR_ARRIVE(a) \
    asm volatile("mbarrier.arrive.shared.b64 _, [%0];" :: "r"(a) : "memory")
#define MBAR_WAIT(a, par) do {                                                   \
    asm volatile(                                                                \
        "{\n\t.reg .pred P1;\n\t"                                                \
        "WL_%=:\n\t"                                                             \
        "mbarrier.try_wait.parity.acquire.cta.shared::cta.b64 P1, [%0], %1, 0x989680;\n\t" \
        "@P1 bra.uni WD_%=;\n\t"                                                 \
        "bra.uni WL_%=;\n\t"                                                     \
        "WD_%=:\n\t}"                                                            \
        :: "r"(a), "r"(par) : "memory");                                         \
} while (0)
#define BULK_G2S(dst, src, bytes, mbar) \
    asm volatile("cp.async.bulk.shared::cta.global.mbarrier::complete_tx::bytes " \
                 "[%0], [%1], %2, [%3];" \
                 :: "r"(dst), "l"(src), "r"(bytes), "r"(mbar) : "memory")

static __device__ __forceinline__ uint32_t smem_u32(const void* p) {
    uint32_t a;
    asm("{ .reg .u64 t; cvta.to.shared.u64 t, %1; cvt.u32.u64 %0, t; }" : "=r"(a) : "l"(p));
    return a;
}

// ---------------------------------------------------------------------------
// Kernel 1: gate partials. grid = 128 blocks x 544 threads (single wave).
// Block (g*2 + half) owns rows [g*128, +128) and H-half [half*2048, +2048).
//
// KEY CHANGE vs R13: rows are pipelined in GROUPS OF 4. Previous rounds all
// paid a ~700-cycle serial latency chain (wait -> LDS -> FMA -> 5 dependent
// SHFLs -> barrier) PER ROW with all warps in lockstep; now one group pays it
// once for 4 rows (4 independent chains interleaved, ILP-4), so the chain
// amortizes 4x and the DRAM floor (~192 cyc/row/SM) becomes the binder.
//
// Ring: 4 group-slots x 32KB (16 row-stages, 128KB dynamic smem). Producer
// (warp 16, lane 0) per group: wait empty[slot], expect_tx(32KB), 4x 8KB
// cp.async.bulk -> full[slot]; runs up to 4 groups (16 rows) ahead.
// Consumers (warps 0-15): per group ONE full-wait, 4x LDS128, 4x16 packed
// FMAs, 4 interleaved 9-shfl distribute-reduce trees (lane l holds expert
// bitrev3(l)), s_part (double-buffered), ONE bar.sync 1,512, release
// empty[slot], then stage-2 (32 parallel (row,expert) reductions) -> g_part.
// ---------------------------------------------------------------------------
__global__ __launch_bounds__(544, 1) void gate_kernel(
    const float* __restrict__ hidden,
    const float* __restrict__ gw)     // (H, E) row-major
{
    extern __shared__ __align__(16) unsigned char dynsmem[];
    float* s_tile = reinterpret_cast<float*>(dynsmem);            // [16][2048]
    float* s_part = reinterpret_cast<float*>(dynsmem + SM_PART_OFF); // [2][4][16][9]

    const int t    = threadIdx.x;
    const int half = (int)blockIdx.x & 1;
    const int base_row = ((int)blockIdx.x >> 1) * RPB;

    const uint32_t mb    = smem_u32(dynsmem + SM_MBAR_OFF);  // full[0..3], empty[4..7]
    const uint32_t tile0 = smem_u32(dynsmem);

    if (t == 0) {
#pragma unroll
        for (int s = 0; s < 4; s++) {
            MBAR_INIT(mb + s * 8, 1);            // full[s]: completed by 32KB tx
            MBAR_INIT(mb + 32 + s * 8, 1);       // empty[s]: 1 release arrival
        }
        asm volatile("fence.proxy.async.shared::cta;" ::: "memory");
    }
    __syncthreads();

    if (t >= 512) {
        // ---- producer warp: lane 0 only, runs up to 4 groups ahead ----
        if (t == 512) {
            const char* src = reinterpret_cast<const char*>(
                hidden + (size_t)base_row * HDIM + (size_t)half * 2048);
            for (int g = 0; g < NGRP; g++) {
                const int slot = g & 3;
                const int ph = ((g >> 2) & 1) ^ 1;  // fresh-mbar: first 4 pass
                MBAR_WAIT(mb + 32 + slot * 8, ph);
                MBAR_EXPECT_TX(mb + slot * 8, 32768);
#pragma unroll
                for (int r4 = 0; r4 < 4; r4++)
                    BULK_G2S(tile0 + (slot * 4 + r4) * 8192,
                             src + (size_t)(g * 4 + r4) * (HDIM * 4), 8192,
                             mb + slot * 8);
            }
        }
        return;
    }

    // ---- consumers: warps 0-15 ----
    const int lane = t & 31;
    const int wid  = t >> 5;
    // expert index held by this lane after the distribute-reduce: bitrev3(lane)
    const int e_lane = ((lane & 1) << 2) | (lane & 2) | ((lane >> 2) & 1);

    // 32 contiguous gate weights for this thread's 4 h positions -> 16 f32x2.
    long long g2[16];
    {
        const long long* gwp =
            reinterpret_cast<const long long*>(gw) + ((size_t)half * 512 + t) * 16;
#pragma unroll
        for (int i = 0; i < 16; i++) g2[i] = gwp[i];
    }

    for (int g = 0; g < NGRP; g++) {
        const int slot = g & 3;
        const int par  = (g >> 2) & 1;
        const int buf  = g & 1;

        MBAR_WAIT(mb + slot * 8, par);

        // 4 rows' float4 loads (independent)
        float4 v[4];
#pragma unroll
        for (int i = 0; i < 4; i++)
            v[i] = *reinterpret_cast<const float4*>(
                &s_tile[(slot * 4 + i) * 2048 + t * 4]);

        // acc[i][j] holds row i, experts {2j,2j+1} packed. 16 independent chains.
        long long acc[4][4];
#pragma unroll
        for (int i = 0; i < 4; i++)
#pragma unroll
            for (int j = 0; j < 4; j++) acc[i][j] = 0;

#pragma unroll
        for (int k = 0; k < 4; k++) {
#pragma unroll
            for (int i = 0; i < 4; i++) {
                const float vk = (k == 0) ? v[i].x : (k == 1) ? v[i].y
                               : (k == 2) ? v[i].z : v[i].w;
                long long pv;
                PACK2(pv, __float_as_int(vk));
                FMA2(acc[i][0], pv, g2[k * 4 + 0], acc[i][0]);
                FMA2(acc[i][1], pv, g2[k * 4 + 1], acc[i][1]);
                FMA2(acc[i][2], pv, g2[k * 4 + 2], acc[i][2]);
                FMA2(acc[i][3], pv, g2[k * 4 + 3], acc[i][3]);
            }
        }

        // 4 interleaved distribute-reduce trees (independent -> ILP-4)
        float val[4];
#pragma unroll
        for (int i = 0; i < 4; i++) {
            long long a0 = acc[i][0], a1 = acc[i][1], a2 = acc[i][2], a3 = acc[i][3];
            {   // level 0: xor 1
                const bool hi = lane & 1;
                long long s0 = hi ? a0 : a2;
                long long s1 = hi ? a1 : a3;
                long long q0 = __shfl_xor_sync(0xffffffffu, s0, 1);
                long long q1 = __shfl_xor_sync(0xffffffffu, s1, 1);
                long long k0 = hi ? a2 : a0;
                long long k1 = hi ? a3 : a1;
                ADD2(a0, k0, q0);
                ADD2(a1, k1, q1);
            }
            {   // level 1: xor 2
                const bool hi = lane & 2;
                long long s0 = hi ? a0 : a1;
                long long q0 = __shfl_xor_sync(0xffffffffu, s0, 2);
                long long k0 = hi ? a1 : a0;
                ADD2(a0, k0, q0);
            }
            {   // level 2: xor 4, unpack
                int lo_i, hi_i;
                UNPK2(lo_i, hi_i, a0);
                const float f0 = __int_as_float(lo_i);
                const float f1 = __int_as_float(hi_i);
                const bool hi = lane & 4;
                const float sv = hi ? f0 : f1;
                const float q = __shfl_xor_sync(0xffffffffu, sv, 4);
                val[i] = (hi ? f1 : f0) + q;
            }
            val[i] += __shfl_xor_sync(0xffffffffu, val[i], 8);
            val[i] += __shfl_xor_sync(0xffffffffu, val[i], 16);
        }

        if (lane < 8) {
#pragma unroll
            for (int i = 0; i < 4; i++)
                s_part[((buf * 4 + i) * 16 + wid) * 9 + e_lane] = val[i];
        }

        asm volatile("bar.sync 1, 512;" ::: "memory");
        // Barrier proves all warps' LDS of this slot completed -> release it
        // now so the producer refills while we do stage-2 + the next group.
        if (t == 0) MBAR_ARRIVE(mb + 32 + slot * 8);

        // stage 2: 32 (row,expert) reductions of 16 warp-partials each.
        // Double-buffered s_part -> no trailing barrier needed.
#pragma unroll
        for (int it = 0; it < 2; it++) {
            const int pid  = wid + it * 16;
            const int row4 = pid >> 3;
            const int e    = pid & 7;
            float p = (lane < 16) ? s_part[((buf * 4 + row4) * 16 + lane) * 9 + e]
                                  : 0.0f;
            p += __shfl_xor_sync(0xffffffffu, p, 8);
            p += __shfl_xor_sync(0xffffffffu, p, 4);
            p += __shfl_xor_sync(0xffffffffu, p, 2);
            p += __shfl_xor_sync(0xffffffffu, p, 1);
            if (lane == 0)
                g_part[(size_t)(base_row + g * 4 + row4) * 16 + half * 8 + e] = p;
        }
    }
}

// ---------------------------------------------------------------------------
// Kernel 2: finalize top-2 + combine. One block per row, 256 threads.
// Warp 0 preamble: score[e] = part[half0] + part[half1] + bias, shfl top-2
// with smallest-index tie-break (matches lax.top_k), 2-way softmax
// (== softmax over 8 + top-2 renorm). Then streaming combine:
// out[b,:] = p0*eo[i0,b,:] + p1*eo[i1,b,:], float4, 8 loads in flight,
// .cs hints (no reuse). Already at the practical DRAM ceiling (~6.5TB/s).
// ---------------------------------------------------------------------------
__global__ __launch_bounds__(256) void combine_kernel(
    const float* __restrict__ eo,
    const float* __restrict__ gb,
    float* __restrict__ out)
{
    const int b = (int)blockIdx.x;
    __shared__ float4 bc;

    if (threadIdx.x < 32) {
        const int lane = threadIdx.x;
        float s = -3.402823466e38f;
        if (lane < 8)
            s = g_part[(size_t)b * 16 + lane] + g_part[(size_t)b * 16 + 8 + lane]
                + gb[lane];

        float v1 = s; int i1 = lane;
#pragma unroll
        for (int off = 4; off; off >>= 1) {
            const float ov = __shfl_xor_sync(0xffffffffu, v1, off);
            const int   oi = __shfl_xor_sync(0xffffffffu, i1, off);
            if (ov > v1 || (ov == v1 && oi < i1)) { v1 = ov; i1 = oi; }
        }
        float v2 = (lane == i1) ? -3.402823466e38f : s;
        int i2 = lane;
#pragma unroll
        for (int off = 4; off; off >>= 1) {
            const float ov = __shfl_xor_sync(0xffffffffu, v2, off);
            const int   oi = __shfl_xor_sync(0xffffffffu, i2, off);
            if (ov > v2 || (ov == v2 && oi < i2)) { v2 = ov; i2 = oi; }
        }
        if (lane == 0) {
            const float p1 = 1.0f / (1.0f + expf(v2 - v1));
            bc = make_float4(p1, 1.0f - p1, __int_as_float(i1), __int_as_float(i2));
        }
    }
    __syncthreads();

    const float4 rg = bc;
    const float p0 = rg.x, p1 = rg.y;
    const int i0 = __float_as_int(rg.z);
    const int i1 = __float_as_int(rg.w);

    const float4* e0 =
        reinterpret_cast<const float4*>(eo + ((size_t)i0 * B_ROWS + b) * HDIM);
    const float4* e1 =
        reinterpret_cast<const float4*>(eo + ((size_t)i1 * B_ROWS + b) * HDIM);
    float4* o = reinterpret_cast<float4*>(out + (size_t)b * HDIM);

    const int t = threadIdx.x;
    float4 a[4], c[4];
#pragma unroll
    for (int k = 0; k < 4; k++) {
        a[k] = __ldcs(&e0[t + k * 256]);
        c[k] = __ldcs(&e1[t + k * 256]);
    }
#pragma unroll
    for (int k = 0; k < 4; k++) {
        float4 r;
        r.x = p0 * a[k].x + p1 * c[k].x;
        r.y = p0 * a[k].y + p1 * c[k].y;
        r.z = p0 * a[k].z + p1 * c[k].z;
        r.w = p0 * a[k].w + p1 * c[k].w;
        __stcs(&o[t + k * 256], r);
    }
}

// ---------------------------------------------------------------------------
// Launch. Inputs (metadata order): hidden_states (B,H) f32, expert_outputs
// (E,B,H) f32, gate_w (H,E) f32, gate_b (E,) f32. Output: (B,H) f32.
// cudaFuncSetAttribute is a non-stream API (executes immediately, not
// captured) -> graph-capture safe. No allocs, no syncs.
// ---------------------------------------------------------------------------
extern "C" void kernel_launch(void* const* d_in, const int* in_sizes, int n_in,
                              void* d_out, int out_size)
{
    const float* hidden = (const float*)d_in[0];
    const float* eo     = (const float*)d_in[1];
    const float* gw     = (const float*)d_in[2];
    const float* gb     = (const float*)d_in[3];
    float* out = (float*)d_out;

    static bool attr_set = false;
    if (!attr_set) {
        cudaFuncSetAttribute(gate_kernel,
                             cudaFuncAttributeMaxDynamicSharedMemorySize,
                             SMEM_BYTES);
        attr_set = true;
    }

    gate_kernel<<<128, 544, SMEM_BYTES>>>(hidden, gw);
    combine_kernel<<<B_ROWS, 256>>>(eo, gb, out);
}